// round 15
// baseline (speedup 1.0000x reference)
#include <cuda_runtime.h>
#include <cuda_fp16.h>
#include <math.h>
#include <stdint.h>

// ---------------- problem constants ----------------
#define Bz 32
#define TE 2048
#define TDd 64
#define Dd 1024
#define Mrows (Bz * TE)      // 65536

// ---------------- scratch (device globals) ----------------
__device__ __half g_A1[(size_t)Mrows * Dd];   // fp16(enc)
__device__ __half g_B1[(size_t)Dd * Dd];      // W^T fp16 : [n][k]
__device__ float g_dU[Bz * Dd];
__device__ float g_scores[Bz * TE];
__device__ float g_weights[Bz * TE];

// ---------------- helpers ----------------
__device__ __forceinline__ uint32_t smem_to_u32(const void* p) {
    uint32_t a;
    asm("{ .reg .u64 t; cvta.to.shared.u64 t, %1; cvt.u32.u64 %0, t; }" : "=r"(a) : "l"(p));
    return a;
}
__device__ __forceinline__ void cp16(uint32_t s, const void* g) {
    asm volatile("cp.async.cg.shared.global [%0], [%1], 16;" :: "r"(s), "l"(g));
}
#define CP_COMMIT() asm volatile("cp.async.commit_group;" ::: "memory")
#define CP_WAIT(n)  asm volatile("cp.async.wait_group %0;" :: "n"(n) : "memory")
#define LDSM_X4(r0, r1, r2, r3, addr) \
    asm volatile("ldmatrix.sync.aligned.m8n8.x4.shared.b16 {%0,%1,%2,%3}, [%4];" \
        : "=r"(r0), "=r"(r1), "=r"(r2), "=r"(r3) : "r"(addr))
#define MMA16816F(d0, d1, d2, d3, a0, a1, a2, a3, b0, b1) \
    asm volatile("mma.sync.aligned.m16n8k16.row.col.f32.f16.f16.f32 " \
        "{%0,%1,%2,%3}, {%4,%5,%6,%7}, {%8,%9}, {%0,%1,%2,%3};" \
        : "+f"(d0), "+f"(d1), "+f"(d2), "+f"(d3) \
        : "r"(a0), "r"(a1), "r"(a2), "r"(a3), "r"(b0), "r"(b1))

__device__ __forceinline__ uint32_t sw128(uint32_t off) {
    return off ^ ((off >> 3) & 0x70);
}
__device__ __forceinline__ float fast_tanh(float x) {
    float ax = fabsf(x);
    float e  = __expf(2.0f * ax);
    float t  = 1.0f - __fdividef(2.0f, e + 1.0f);
    return copysignf(t, x);
}

// ---------------- GEMM tiling (round-13 frozen config) ----------------
#define BM 128
#define BN 128
#define BKE 64                      // fp16 k per chunk (128 B rows)
#define NKC1 16                     // 16 k-chunks
#define STG_B 32768                 // per-stage bytes: A 16K + B 16K
#define SMEM_TOTAL (3 * STG_B)      // 96 KB
#define GTHREADS 128                // 4 warps, 2x2 warp grid, 64x64 warp tile

// ---------------- fused prologue ----------------
// blocks [0, NB_A)            : convert_A (+ zero scores / out_context)
// blocks [NB_A, NB_A+NB_W)    : W transpose fp32->fp16
// blocks [NB_A+NB_W, .. +NB_D): dU (atomic-free)
#define NB_A 32768
#define NB_W 1024
#define NB_D 128
#define NB_TOTAL (NB_A + NB_W + NB_D)

__global__ void prologue_kernel(const float* __restrict__ enc,
                                const float* __restrict__ W,
                                const float* __restrict__ dec,
                                const float* __restrict__ U,
                                float* __restrict__ out_context) {
    __shared__ float tile[32][33];
    const int bid = blockIdx.x;
    const int tid = threadIdx.x;

    if (bid < NB_A) {
        // ---- convert_A: 8 floats per thread ----
        size_t i = ((size_t)bid * 256 + tid) * 8;
        float4 v0 = *(const float4*)(enc + i);
        float4 v1 = *(const float4*)(enc + i + 4);
        __half2 h[4];
        h[0] = __floats2half2_rn(v0.x, v0.y);
        h[1] = __floats2half2_rn(v0.z, v0.w);
        h[2] = __floats2half2_rn(v1.x, v1.y);
        h[3] = __floats2half2_rn(v1.z, v1.w);
        *(uint4*)(g_A1 + i) = *(uint4*)h;
        // zeroing duties (consumed only by later launches)
        if (bid < 256) g_scores[bid * 256 + tid] = 0.0f;
        if (bid < 128) out_context[bid * 256 + tid] = 0.0f;
    } else if (bid < NB_A + NB_W) {
        // ---- W transpose: W[k][n] -> B1[n][k] fp16, tiled ----
        const int wb = bid - NB_A;
        const int n0 = (wb & 31) * 32, k0 = (wb >> 5) * 32;
        const int tx = tid & 31, ty = tid >> 5;      // 32 x 8
#pragma unroll
        for (int j = 0; j < 4; j++)
            tile[ty + 8 * j][tx] = W[(size_t)(k0 + ty + 8 * j) * Dd + n0 + tx];
        __syncthreads();
#pragma unroll
        for (int j = 0; j < 4; j++)
            g_B1[(size_t)(n0 + ty + 8 * j) * Dd + k0 + tx] =
                __float2half(tile[tx][ty + 8 * j]);
    } else {
        // ---- dU: one thread per (b, f), atomic-free ----
        int g = (bid - NB_A - NB_W) * 256 + tid;     // 0..32767
        int b = g >> 10, f = g & 1023;
        const float* dvec = dec + ((size_t)b * TDd + (TDd - 1)) * Dd;
        float acc = 0.0f;
#pragma unroll 8
        for (int k = 0; k < Dd; k++)
            acc = fmaf(dvec[k], U[(size_t)k * Dd + f], acc);
        g_dU[b * Dd + f] = acc;
    }
}

// ---------------- fused GEMM + epilogue (round-13, unchanged) ----------------
__device__ __forceinline__ void load_chunk(uint32_t sbase, int stage, int c,
                                           int mbase, int nbase, int tid) {
    const int kb = c * BKE;
    uint32_t sA = sbase + stage * STG_B;
    uint32_t sB = sA + 16384;
#pragma unroll
    for (int i = 0; i < 8; i++) {
        int u = tid + i * GTHREADS;            // 0..1023
        int r = u >> 3, ch = u & 7;
        uint32_t off = sw128((uint32_t)(r * 128 + ch * 16));
        cp16(sA + off, g_A1 + (size_t)(mbase + r) * Dd + kb + ch * 8);
        cp16(sB + off, g_B1 + (size_t)(nbase + r) * Dd + kb + ch * 8);
    }
    CP_COMMIT();
}

__global__ void __launch_bounds__(GTHREADS, 2) gemm_score_mma(const float* __restrict__ V) {
    extern __shared__ char smem[];
    uint32_t sbase = smem_to_u32(smem);

    const int tid  = threadIdx.x;
    const int wid  = tid >> 5;      // 0..3
    const int lane = tid & 31;
    const int wm   = wid >> 1;      // 0..1 : 64 rows
    const int wn   = wid & 1;       // 0..1 : 64 cols

    const int nblk  = blockIdx.x & 7;
    const int mblk  = blockIdx.x >> 3;
    const int mbase = mblk * BM;
    const int nbase = nblk * BN;
    const int b     = mbase >> 11;

    float acc[4][8][4];
#pragma unroll
    for (int mt = 0; mt < 4; mt++)
#pragma unroll
        for (int nt = 0; nt < 8; nt++)
#pragma unroll
            for (int i = 0; i < 4; i++) acc[mt][nt][i] = 0.0f;

    const int a_r  = lane & 15;
    const int a_kc = lane >> 4;
    const int b_n  = ((lane >> 4) & 1) * 8 + (lane & 7);
    const int b_kc = (lane >> 3) & 1;

    load_chunk(sbase, 0, 0, mbase, nbase, tid);
    load_chunk(sbase, 1, 1, mbase, nbase, tid);

    int stage = 0;
    for (int c = 0; c < NKC1; c++) {
        if (c + 2 < NKC1) { CP_WAIT(1); } else { CP_WAIT(0); }
        __syncthreads();
        if (c + 2 < NKC1) {
            int ns = stage + 2; if (ns >= 3) ns -= 3;
            load_chunk(sbase, ns, c + 2, mbase, nbase, tid);
        }

        const uint32_t sA = sbase + stage * STG_B;
        const uint32_t sB = sA + 16384;
#pragma unroll
        for (int ks = 0; ks < 4; ks++) {
            uint32_t af[4][4], bf[4][4];
#pragma unroll
            for (int mt = 0; mt < 4; mt++) {
                int row = wm * 64 + mt * 16 + a_r;
                uint32_t off = sw128((uint32_t)(row * 128 + (ks * 2 + a_kc) * 16));
                LDSM_X4(af[mt][0], af[mt][1], af[mt][2], af[mt][3], sA + off);
            }
#pragma unroll
            for (int p = 0; p < 4; p++) {
                int row = wn * 64 + p * 16 + b_n;
                uint32_t off = sw128((uint32_t)(row * 128 + (ks * 2 + b_kc) * 16));
                LDSM_X4(bf[p][0], bf[p][1], bf[p][2], bf[p][3], sB + off);
            }
#pragma unroll
            for (int mt = 0; mt < 4; mt++)
#pragma unroll
                for (int nt = 0; nt < 8; nt++)
                    MMA16816F(acc[mt][nt][0], acc[mt][nt][1], acc[mt][nt][2], acc[mt][nt][3],
                              af[mt][0], af[mt][1], af[mt][2], af[mt][3],
                              bf[nt >> 1][(nt & 1) * 2], bf[nt >> 1][(nt & 1) * 2 + 1]);
        }
        stage++; if (stage >= 3) stage = 0;
    }

    // ---- fused epilogue ----
    const int q = lane >> 2;
    const int t4 = lane & 3;
#pragma unroll
    for (int mt = 0; mt < 4; mt++) {
        float s0 = 0.0f, s1 = 0.0f;
#pragma unroll
        for (int nt = 0; nt < 8; nt++) {
            int n0 = nbase + wn * 64 + nt * 8 + 2 * t4;
            float v0 = V[n0], v1 = V[n0 + 1];
            float u0 = g_dU[b * Dd + n0], u1 = g_dU[b * Dd + n0 + 1];
            s0 = fmaf(v0, fast_tanh(acc[mt][nt][0] + u0), s0);
            s0 = fmaf(v1, fast_tanh(acc[mt][nt][1] + u1), s0);
            s1 = fmaf(v0, fast_tanh(acc[mt][nt][2] + u0), s1);
            s1 = fmaf(v1, fast_tanh(acc[mt][nt][3] + u1), s1);
        }
        s0 += __shfl_xor_sync(0xFFFFFFFF, s0, 1);
        s0 += __shfl_xor_sync(0xFFFFFFFF, s0, 2);
        s1 += __shfl_xor_sync(0xFFFFFFFF, s1, 1);
        s1 += __shfl_xor_sync(0xFFFFFFFF, s1, 2);
        if (t4 == 0) {
            int row = mbase + wm * 64 + mt * 16 + q;
            atomicAdd(&g_scores[row], s0);
            atomicAdd(&g_scores[row + 8], s1);
        }
    }
}

// ---------------- softmax & context ----------------
__global__ void softmax_kernel(float* __restrict__ out_weights) {
    const int b = blockIdx.x;
    const int tid = threadIdx.x;
    __shared__ float red[256];
    float local[8];
    float mx = -INFINITY;
#pragma unroll
    for (int i = 0; i < 8; i++) {
        local[i] = g_scores[b * TE + tid + i * 256];
        mx = fmaxf(mx, local[i]);
    }
    red[tid] = mx;
    __syncthreads();
    for (int s = 128; s > 0; s >>= 1) {
        if (tid < s) red[tid] = fmaxf(red[tid], red[tid + s]);
        __syncthreads();
    }
    mx = red[0];
    __syncthreads();
    float sum = 0.0f;
#pragma unroll
    for (int i = 0; i < 8; i++) { local[i] = __expf(local[i] - mx); sum += local[i]; }
    red[tid] = sum;
    __syncthreads();
    for (int s = 128; s > 0; s >>= 1) {
        if (tid < s) red[tid] += red[tid + s];
        __syncthreads();
    }
    const float inv = 1.0f / red[0];
#pragma unroll
    for (int i = 0; i < 8; i++) {
        float w = local[i] * inv;
        g_weights[b * TE + tid + i * 256]   = w;
        out_weights[b * TE + tid + i * 256] = w;
    }
}

// split-T context: grid (32, 2, 8), block 256
__global__ void context_kernel(float* __restrict__ out_context) {
    const int b  = blockIdx.x;
    const int e2 = blockIdx.y * 256 + threadIdx.x;   // half2 index
    const int t0 = blockIdx.z * 256;

    __shared__ float sw[256];
    sw[threadIdx.x] = g_weights[b * TE + t0 + threadIdx.x];
    __syncthreads();

    const __half2* base = (const __half2*)(g_A1 + (size_t)b * TE * Dd) + e2;
    float ax = 0.0f, ay = 0.0f;
#pragma unroll 8
    for (int t = 0; t < 256; t++) {
        __half2 h = base[(size_t)(t0 + t) * (Dd / 2)];
        float2 f = __half22float2(h);
        ax = fmaf(sw[t], f.x, ax);
        ay = fmaf(sw[t], f.y, ay);
    }
    atomicAdd(&out_context[b * Dd + 2 * e2], ax);
    atomicAdd(&out_context[b * Dd + 2 * e2 + 1], ay);
}

// ---------------- launch ----------------
extern "C" void kernel_launch(void* const* d_in, const int* in_sizes, int n_in,
                              void* d_out, int out_size) {
    const float* enc = (const float*)d_in[0];
    const float* dec = (const float*)d_in[1];
    const float* W_a = (const float*)d_in[2];
    const float* U_a = (const float*)d_in[3];
    const float* V_a = (const float*)d_in[4];
    float* out = (float*)d_out;
    float* out_context = out;            // 32*1024
    float* out_weights = out + Bz * Dd;  // 32*2048

    static int smem_set = 0;
    if (!smem_set) {
        cudaFuncSetAttribute(gemm_score_mma, cudaFuncAttributeMaxDynamicSharedMemorySize, SMEM_TOTAL);
        smem_set = 1;
    }

    prologue_kernel<<<NB_TOTAL, 256>>>(enc, W_a, dec, U_a, out_context);
    gemm_score_mma<<<(Mrows / BM) * (Dd / BN), GTHREADS, SMEM_TOTAL>>>(V_a);
    softmax_kernel<<<Bz, 256>>>(out_weights);
    {
        dim3 g(Bz, 2, 8);
        context_kernel<<<g, 256>>>(out_context);
    }
}

// round 16
// speedup vs baseline: 1.0438x; 1.0438x over previous
#include <cuda_runtime.h>
#include <cuda_fp16.h>
#include <math.h>
#include <stdint.h>

// ---------------- problem constants ----------------
#define Bz 32
#define TE 2048
#define TDd 64
#define Dd 1024
#define Mrows (Bz * TE)      // 65536

// ---------------- scratch (device globals) ----------------
__device__ __half g_A1[(size_t)Mrows * Dd];   // fp16(enc)
__device__ __half g_B1[(size_t)Dd * Dd];      // W^T fp16 : [n][k]
__device__ float g_dU[Bz * Dd];
__device__ float g_scores[Bz * TE];
__device__ float g_weights[Bz * TE];

// ---------------- helpers ----------------
__device__ __forceinline__ uint32_t smem_to_u32(const void* p) {
    uint32_t a;
    asm("{ .reg .u64 t; cvta.to.shared.u64 t, %1; cvt.u32.u64 %0, t; }" : "=r"(a) : "l"(p));
    return a;
}
__device__ __forceinline__ void cp16(uint32_t s, const void* g) {
    asm volatile("cp.async.cg.shared.global [%0], [%1], 16;" :: "r"(s), "l"(g));
}
#define CP_COMMIT() asm volatile("cp.async.commit_group;" ::: "memory")
#define CP_WAIT(n)  asm volatile("cp.async.wait_group %0;" :: "n"(n) : "memory")
#define LDSM_X4(r0, r1, r2, r3, addr) \
    asm volatile("ldmatrix.sync.aligned.m8n8.x4.shared.b16 {%0,%1,%2,%3}, [%4];" \
        : "=r"(r0), "=r"(r1), "=r"(r2), "=r"(r3) : "r"(addr))
#define MMA16816F(d0, d1, d2, d3, a0, a1, a2, a3, b0, b1) \
    asm volatile("mma.sync.aligned.m16n8k16.row.col.f32.f16.f16.f32 " \
        "{%0,%1,%2,%3}, {%4,%5,%6,%7}, {%8,%9}, {%0,%1,%2,%3};" \
        : "+f"(d0), "+f"(d1), "+f"(d2), "+f"(d3) \
        : "r"(a0), "r"(a1), "r"(a2), "r"(a3), "r"(b0), "r"(b1))

__device__ __forceinline__ uint32_t sw128(uint32_t off) {
    return off ^ ((off >> 3) & 0x70);
}
__device__ __forceinline__ float fast_tanh(float x) {
    float ax = fabsf(x);
    float e  = __expf(2.0f * ax);
    float t  = 1.0f - __fdividef(2.0f, e + 1.0f);
    return copysignf(t, x);
}

// ---------------- GEMM tiling (frozen round-13 config) ----------------
#define BM 128
#define BN 128
#define BKE 64                      // fp16 k per chunk (128 B rows)
#define NKC1 16                     // 16 k-chunks
#define STG_B 32768                 // per-stage bytes: A 16K + B 16K
#define SMEM_TOTAL (3 * STG_B)      // 96 KB
#define GTHREADS 128                // 4 warps, 2x2 warp grid, 64x64 warp tile

// ---------------- fused prologue (long-latency roles FIRST) ----------------
// blocks [0, NB_D)                 : dU (atomic-free, U reads mostly L2-resident)
// blocks [NB_D, NB_D+NB_W)         : W transpose fp32->fp16
// blocks [NB_D+NB_W, NB_TOTAL)     : convert_A (+ zero scores / out_context)
#define NB_D 128
#define NB_W 1024
#define NB_A 32768
#define NB_TOTAL (NB_D + NB_W + NB_A)

__global__ void prologue_kernel(const float* __restrict__ enc,
                                const float* __restrict__ W,
                                const float* __restrict__ dec,
                                const float* __restrict__ U,
                                float* __restrict__ out_context) {
    __shared__ float tile[32][33];
    const int bid = blockIdx.x;
    const int tid = threadIdx.x;

    if (bid < NB_D) {
        // ---- dU: one thread per (b, f), atomic-free ----
        int g = bid * 256 + tid;                     // 0..32767
        int b = g >> 10, f = g & 1023;
        const float* dvec = dec + ((size_t)b * TDd + (TDd - 1)) * Dd;
        float acc = 0.0f;
#pragma unroll 8
        for (int k = 0; k < Dd; k++)
            acc = fmaf(dvec[k], U[(size_t)k * Dd + f], acc);
        g_dU[b * Dd + f] = acc;
    } else if (bid < NB_D + NB_W) {
        // ---- W transpose: W[k][n] -> B1[n][k] fp16, tiled ----
        const int wb = bid - NB_D;
        const int n0 = (wb & 31) * 32, k0 = (wb >> 5) * 32;
        const int tx = tid & 31, ty = tid >> 5;      // 32 x 8
#pragma unroll
        for (int j = 0; j < 4; j++)
            tile[ty + 8 * j][tx] = W[(size_t)(k0 + ty + 8 * j) * Dd + n0 + tx];
        __syncthreads();
#pragma unroll
        for (int j = 0; j < 4; j++)
            g_B1[(size_t)(n0 + ty + 8 * j) * Dd + k0 + tx] =
                __float2half(tile[tx][ty + 8 * j]);
    } else {
        // ---- convert_A: 8 floats per thread ----
        const int ab = bid - NB_D - NB_W;            // 0..32767
        size_t i = ((size_t)ab * 256 + tid) * 8;
        float4 v0 = *(const float4*)(enc + i);
        float4 v1 = *(const float4*)(enc + i + 4);
        __half2 h[4];
        h[0] = __floats2half2_rn(v0.x, v0.y);
        h[1] = __floats2half2_rn(v0.z, v0.w);
        h[2] = __floats2half2_rn(v1.x, v1.y);
        h[3] = __floats2half2_rn(v1.z, v1.w);
        *(uint4*)(g_A1 + i) = *(uint4*)h;
        if (ab < 256) g_scores[ab * 256 + tid] = 0.0f;
        if (ab < 128) out_context[ab * 256 + tid] = 0.0f;
    }
}

// ---------------- fused GEMM + epilogue (round-13, unchanged) ----------------
__device__ __forceinline__ void load_chunk(uint32_t sbase, int stage, int c,
                                           int mbase, int nbase, int tid) {
    const int kb = c * BKE;
    uint32_t sA = sbase + stage * STG_B;
    uint32_t sB = sA + 16384;
#pragma unroll
    for (int i = 0; i < 8; i++) {
        int u = tid + i * GTHREADS;            // 0..1023
        int r = u >> 3, ch = u & 7;
        uint32_t off = sw128((uint32_t)(r * 128 + ch * 16));
        cp16(sA + off, g_A1 + (size_t)(mbase + r) * Dd + kb + ch * 8);
        cp16(sB + off, g_B1 + (size_t)(nbase + r) * Dd + kb + ch * 8);
    }
    CP_COMMIT();
}

__global__ void __launch_bounds__(GTHREADS, 2) gemm_score_mma(const float* __restrict__ V) {
    extern __shared__ char smem[];
    uint32_t sbase = smem_to_u32(smem);

    const int tid  = threadIdx.x;
    const int wid  = tid >> 5;      // 0..3
    const int lane = tid & 31;
    const int wm   = wid >> 1;      // 0..1 : 64 rows
    const int wn   = wid & 1;       // 0..1 : 64 cols

    const int nblk  = blockIdx.x & 7;
    const int mblk  = blockIdx.x >> 3;
    const int mbase = mblk * BM;
    const int nbase = nblk * BN;
    const int b     = mbase >> 11;

    float acc[4][8][4];
#pragma unroll
    for (int mt = 0; mt < 4; mt++)
#pragma unroll
        for (int nt = 0; nt < 8; nt++)
#pragma unroll
            for (int i = 0; i < 4; i++) acc[mt][nt][i] = 0.0f;

    const int a_r  = lane & 15;
    const int a_kc = lane >> 4;
    const int b_n  = ((lane >> 4) & 1) * 8 + (lane & 7);
    const int b_kc = (lane >> 3) & 1;

    load_chunk(sbase, 0, 0, mbase, nbase, tid);
    load_chunk(sbase, 1, 1, mbase, nbase, tid);

    int stage = 0;
    for (int c = 0; c < NKC1; c++) {
        if (c + 2 < NKC1) { CP_WAIT(1); } else { CP_WAIT(0); }
        __syncthreads();
        if (c + 2 < NKC1) {
            int ns = stage + 2; if (ns >= 3) ns -= 3;
            load_chunk(sbase, ns, c + 2, mbase, nbase, tid);
        }

        const uint32_t sA = sbase + stage * STG_B;
        const uint32_t sB = sA + 16384;
#pragma unroll
        for (int ks = 0; ks < 4; ks++) {
            uint32_t af[4][4], bf[4][4];
#pragma unroll
            for (int mt = 0; mt < 4; mt++) {
                int row = wm * 64 + mt * 16 + a_r;
                uint32_t off = sw128((uint32_t)(row * 128 + (ks * 2 + a_kc) * 16));
                LDSM_X4(af[mt][0], af[mt][1], af[mt][2], af[mt][3], sA + off);
            }
#pragma unroll
            for (int p = 0; p < 4; p++) {
                int row = wn * 64 + p * 16 + b_n;
                uint32_t off = sw128((uint32_t)(row * 128 + (ks * 2 + b_kc) * 16));
                LDSM_X4(bf[p][0], bf[p][1], bf[p][2], bf[p][3], sB + off);
            }
#pragma unroll
            for (int mt = 0; mt < 4; mt++)
#pragma unroll
                for (int nt = 0; nt < 8; nt++)
                    MMA16816F(acc[mt][nt][0], acc[mt][nt][1], acc[mt][nt][2], acc[mt][nt][3],
                              af[mt][0], af[mt][1], af[mt][2], af[mt][3],
                              bf[nt >> 1][(nt & 1) * 2], bf[nt >> 1][(nt & 1) * 2 + 1]);
        }
        stage++; if (stage >= 3) stage = 0;
    }

    // ---- fused epilogue ----
    const int q = lane >> 2;
    const int t4 = lane & 3;
#pragma unroll
    for (int mt = 0; mt < 4; mt++) {
        float s0 = 0.0f, s1 = 0.0f;
#pragma unroll
        for (int nt = 0; nt < 8; nt++) {
            int n0 = nbase + wn * 64 + nt * 8 + 2 * t4;
            float v0 = V[n0], v1 = V[n0 + 1];
            float u0 = g_dU[b * Dd + n0], u1 = g_dU[b * Dd + n0 + 1];
            s0 = fmaf(v0, fast_tanh(acc[mt][nt][0] + u0), s0);
            s0 = fmaf(v1, fast_tanh(acc[mt][nt][1] + u1), s0);
            s1 = fmaf(v0, fast_tanh(acc[mt][nt][2] + u0), s1);
            s1 = fmaf(v1, fast_tanh(acc[mt][nt][3] + u1), s1);
        }
        s0 += __shfl_xor_sync(0xFFFFFFFF, s0, 1);
        s0 += __shfl_xor_sync(0xFFFFFFFF, s0, 2);
        s1 += __shfl_xor_sync(0xFFFFFFFF, s1, 1);
        s1 += __shfl_xor_sync(0xFFFFFFFF, s1, 2);
        if (t4 == 0) {
            int row = mbase + wm * 64 + mt * 16 + q;
            atomicAdd(&g_scores[row], s0);
            atomicAdd(&g_scores[row + 8], s1);
        }
    }
}

// ---------------- softmax & context ----------------
__global__ void softmax_kernel(float* __restrict__ out_weights) {
    const int b = blockIdx.x;
    const int tid = threadIdx.x;
    __shared__ float red[256];
    float local[8];
    float mx = -INFINITY;
#pragma unroll
    for (int i = 0; i < 8; i++) {
        local[i] = g_scores[b * TE + tid + i * 256];
        mx = fmaxf(mx, local[i]);
    }
    red[tid] = mx;
    __syncthreads();
    for (int s = 128; s > 0; s >>= 1) {
        if (tid < s) red[tid] = fmaxf(red[tid], red[tid + s]);
        __syncthreads();
    }
    mx = red[0];
    __syncthreads();
    float sum = 0.0f;
#pragma unroll
    for (int i = 0; i < 8; i++) { local[i] = __expf(local[i] - mx); sum += local[i]; }
    red[tid] = sum;
    __syncthreads();
    for (int s = 128; s > 0; s >>= 1) {
        if (tid < s) red[tid] += red[tid + s];
        __syncthreads();
    }
    const float inv = 1.0f / red[0];
#pragma unroll
    for (int i = 0; i < 8; i++) {
        float w = local[i] * inv;
        g_weights[b * TE + tid + i * 256]   = w;
        out_weights[b * TE + tid + i * 256] = w;
    }
}

// split-T context: grid (32, 2, 32), block 256, 64-t slices
__global__ void context_kernel(float* __restrict__ out_context) {
    const int b  = blockIdx.x;
    const int e2 = blockIdx.y * 256 + threadIdx.x;   // half2 index, 0..511
    const int t0 = blockIdx.z * 64;

    __shared__ float sw[64];
    if (threadIdx.x < 64) sw[threadIdx.x] = g_weights[b * TE + t0 + threadIdx.x];
    __syncthreads();

    const __half2* base = (const __half2*)(g_A1 + (size_t)b * TE * Dd) + e2;
    float ax = 0.0f, ay = 0.0f;
#pragma unroll 8
    for (int t = 0; t < 64; t++) {
        __half2 h = base[(size_t)(t0 + t) * (Dd / 2)];
        float2 f = __half22float2(h);
        ax = fmaf(sw[t], f.x, ax);
        ay = fmaf(sw[t], f.y, ay);
    }
    atomicAdd(&out_context[b * Dd + 2 * e2], ax);
    atomicAdd(&out_context[b * Dd + 2 * e2 + 1], ay);
}

// ---------------- launch ----------------
extern "C" void kernel_launch(void* const* d_in, const int* in_sizes, int n_in,
                              void* d_out, int out_size) {
    const float* enc = (const float*)d_in[0];
    const float* dec = (const float*)d_in[1];
    const float* W_a = (const float*)d_in[2];
    const float* U_a = (const float*)d_in[3];
    const float* V_a = (const float*)d_in[4];
    float* out = (float*)d_out;
    float* out_context = out;            // 32*1024
    float* out_weights = out + Bz * Dd;  // 32*2048

    static int smem_set = 0;
    if (!smem_set) {
        cudaFuncSetAttribute(gemm_score_mma, cudaFuncAttributeMaxDynamicSharedMemorySize, SMEM_TOTAL);
        smem_set = 1;
    }

    prologue_kernel<<<NB_TOTAL, 256>>>(enc, W_a, dec, U_a, out_context);
    gemm_score_mma<<<(Mrows / BM) * (Dd / BN), GTHREADS, SMEM_TOTAL>>>(V_a);
    softmax_kernel<<<Bz, 256>>>(out_weights);
    {
        dim3 g(Bz, 2, 32);
        context_kernel<<<g, 256>>>(out_context);
    }
}